// round 13
// baseline (speedup 1.0000x reference)
#include <cuda_runtime.h>
#include <stdint.h>

// PluginEmbedding: sparse embedding lookup + per-row sum combine.
//   d_in[0] table         float32 [1000000, 128]
//   d_in[1] row_offsets   int32   [212993]
//   d_in[2] value_tensors int32   [212992]
// Output: float32 [212992, 128]
//
// R12: ptxas only encodes L2::evict_last on 256-bit loads (.v8.b32) on
// sm_103a. So: 256-bit evict_last table gathers (protect the ~100MB unique
// table set in L2 against the 109MB evict-first write stream), half-warp per
// row (lane l -> bytes (l&15)*32 of row base+2u+(l>>4)), 2 rows per load
// instruction, 8 rows per 4-load batch. SMEM metadata stage unchanged.

static constexpr int  kVocab        = 1000000;
static constexpr long long kNumRows = 8192LL * 26LL; // 212992
static constexpr int  kRowsPerBlock = 128;           // 1664 blocks (exact)
static constexpr int  kRowBytes     = 512;           // 128 floats

// 256-bit non-coherent load with L2 evict-last (table residency protection).
__device__ __forceinline__ void ldg256_el(const void* p, float4& a, float4& b) {
    unsigned r0, r1, r2, r3, r4, r5, r6, r7;
    asm("ld.global.nc.L2::evict_last.v8.b32 {%0,%1,%2,%3,%4,%5,%6,%7}, [%8];"
        : "=r"(r0), "=r"(r1), "=r"(r2), "=r"(r3),
          "=r"(r4), "=r"(r5), "=r"(r6), "=r"(r7)
        : "l"(p));
    a.x = __uint_as_float(r0); a.y = __uint_as_float(r1);
    a.z = __uint_as_float(r2); a.w = __uint_as_float(r3);
    b.x = __uint_as_float(r4); b.y = __uint_as_float(r5);
    b.z = __uint_as_float(r6); b.w = __uint_as_float(r7);
}

__global__ __launch_bounds__(256, 4) void pe_gather_kernel(
    const float* __restrict__ table,
    const int*   __restrict__ row_offsets,
    const int*   __restrict__ vals,
    float*       __restrict__ out)
{
    __shared__ int s_idx[kRowsPerBlock];
    __shared__ int s_beg[kRowsPerBlock];
    __shared__ int s_end[kRowsPerBlock];

    const int t = threadIdx.x;
    const unsigned blockRow0 = blockIdx.x * kRowsPerBlock;

    // Phase A: coalesced metadata stage (once per block).
    if (t < kRowsPerBlock) {
        const int b = __ldg(&row_offsets[blockRow0 + t]);
        const int e = __ldg(&row_offsets[blockRow0 + t + 1]);
        s_beg[t] = b;
        s_end[t] = e;
        s_idx[t] = (b < e) ? __ldg(&vals[b]) : -1;
    }
    __syncthreads();

    const int warp     = t >> 5;
    const int lane     = t & 31;
    const int halfLane = lane & 15;   // 32B slice within the row
    const int rowSel   = lane >> 4;   // which of the 2 rows this half-warp owns
    const char* tbl = reinterpret_cast<const char*>(table);
    char*       o   = reinterpret_cast<char*>(out);
    const unsigned sliceOff = (unsigned)halfLane * 32u;

    // Phase B: warp owns 16 rows -> 2 batches of 4 loads x 2 rows each.
#pragma unroll
    for (int batch = 0; batch < 2; ++batch) {
        const int base = warp * 16 + batch * 8;

        int idx[4];
#pragma unroll
        for (int u = 0; u < 4; ++u)
            idx[u] = s_idx[base + 2 * u + rowSel];   // LDS, 2 bcast addrs/warp

        // 4 independent 1024B (2-row) gathers, L2 evict-last.
        float4 va[4], vb[4];
#pragma unroll
        for (int u = 0; u < 4; ++u) {
            const unsigned i = (unsigned)((idx[u] >= 0) ? min(idx[u], kVocab - 1) : 0);
            ldg256_el(tbl + i * (unsigned)kRowBytes + sliceOff, va[u], vb[u]);
        }

#pragma unroll
        for (int u = 0; u < 4; ++u) {
            const int r = base + 2 * u + rowSel;     // this lane's row
            float4 a = va[u], b = vb[u];
            if (idx[u] < 0) {
                a = make_float4(0.f, 0.f, 0.f, 0.f);
                b = make_float4(0.f, 0.f, 0.f, 0.f);
            }
            // Generic nnz>1 tail (absent in this dataset, kept for correctness).
            const int e = s_end[r];
            for (int j = s_beg[r] + 1; j < e; ++j) {
                int i = __ldg(&vals[j]);
                i = min(max(i, 0), kVocab - 1);
                float4 ta, tb;
                ldg256_el(tbl + (unsigned)i * (unsigned)kRowBytes + sliceOff, ta, tb);
                a.x += ta.x; a.y += ta.y; a.z += ta.z; a.w += ta.w;
                b.x += tb.x; b.y += tb.y; b.z += tb.z; b.w += tb.w;
            }
            // Output stream: evict-first; lanes 0-15 cover the row contiguously.
            char* dst = o + (blockRow0 + (unsigned)r) * (unsigned)kRowBytes + sliceOff;
            __stcs(reinterpret_cast<float4*>(dst),      a);
            __stcs(reinterpret_cast<float4*>(dst + 16), b);
        }
    }
}

extern "C" void kernel_launch(void* const* d_in, const int* in_sizes, int n_in,
                              void* d_out, int out_size)
{
    const float* table = (const float*)d_in[0];
    const int*   offs  = (const int*)d_in[1];
    const int*   vals  = (const int*)d_in[2];
    float*       out   = (float*)d_out;

    (void)in_sizes; (void)n_in; (void)out_size;

    const int block = 256;
    const unsigned grid = (unsigned)(kNumRows / kRowsPerBlock);   // 1664

    pe_gather_kernel<<<grid, block>>>(table, offs, vals, out);
}